// round 5
// baseline (speedup 1.0000x reference)
#include <cuda_runtime.h>
#include <cuda_bf16.h>
#include <cstdint>

#define Cc 128
#define Gg 2000
#define Hh 256

// ---------------- scratch (device globals; no allocation) ----------------
__device__ float d_ce_g[Cc * 64];             // [128,64]
__device__ float d_A_g[Cc * Hh];              // [128,256]
__device__ float d_B_g[Gg * Hh];              // [2000,256]

__device__ __forceinline__ float eluf(float x) {
    return x > 0.f ? x : (__expf(x) - 1.f);
}

// MUFU-free elu: branchless expm1 via FMA range-reduction + poly + exponent bits.
__device__ __forceinline__ float fast_elu(float x) {
    float t = fmaxf(x, -17.0f);
    // n = round(t * log2(e)) via magic-number trick
    float nf = fmaf(t, 1.4426950408889634f, 12582912.0f);   // + 1.5*2^23
    int   ni = __float_as_int(nf) - 0x4B400000;
    float n  = nf - 12582912.0f;
    // f = t - n*ln2 (split for accuracy)
    float f = fmaf(n, -0.6931471824645996f, t);
    f = fmaf(n, 1.904654323148236e-09f, f);
    // e^f, f in [-0.347, 0.347], degree-6
    float p = 1.3981999507e-3f;
    p = fmaf(p, f, 8.3334519073e-3f);
    p = fmaf(p, f, 4.1665795894e-2f);
    p = fmaf(p, f, 1.6666665459e-1f);
    p = fmaf(p, f, 5.0000001201e-1f);
    p = fmaf(p, f, 1.0f);
    p = fmaf(p, f, 1.0f);
    float s = __int_as_float((ni + 127) << 23);             // 2^n
    float r = fmaf(p, s, -1.0f);                            // e^t - 1
    return x > 0.f ? x : r;
}

__device__ __forceinline__ void mma_tf32(float* acc, const unsigned* a, const unsigned* b) {
    asm volatile(
        "mma.sync.aligned.m16n8k8.row.col.f32.tf32.tf32.f32 "
        "{%0,%1,%2,%3}, {%4,%5,%6,%7}, {%8,%9}, {%0,%1,%2,%3};"
        : "+f"(acc[0]), "+f"(acc[1]), "+f"(acc[2]), "+f"(acc[3])
        : "r"(a[0]), "r"(a[1]), "r"(a[2]), "r"(a[3]), "r"(b[0]), "r"(b[1]));
}

__device__ __forceinline__ uint32_t smem_u32(const void* p) {
    uint32_t a;
    asm("{ .reg .u64 t; cvta.to.shared.u64 t, %1; cvt.u32.u64 %0, t; }" : "=r"(a) : "l"(p));
    return a;
}
__device__ __forceinline__ void cpasync16(uint32_t dst, const void* src) {
    asm volatile("cp.async.ca.shared.global [%0], [%1], 16;" :: "r"(dst), "l"(src));
}
__device__ __forceinline__ void cp_commit() { asm volatile("cp.async.commit_group;"); }
template <int N> __device__ __forceinline__ void cp_wait() {
    asm volatile("cp.async.wait_group %0;" :: "n"(N));
}

// ---------------- k_ce: ce = elu(ctrl@ce_w1+b1)@ce_w2+b2  [128,64] ------
__global__ __launch_bounds__(1024) void k_ce(
    const float* __restrict__ ctrl, const float* __restrict__ ce_w1,
    const float* __restrict__ ce_b1, const float* __restrict__ ce_w2,
    const float* __restrict__ ce_b2)
{
    int c = blockIdx.x, tid = threadIdx.x;
    __shared__ float row[Gg];
    __shared__ float part[4][256];
    __shared__ float h1[256];
    for (int i = tid; i < Gg; i += 1024) row[i] = ctrl[c * Gg + i];
    __syncthreads();
    int sl = tid >> 8, t = tid & 255;
    float acc = 0.f;
    for (int k = sl * 500; k < sl * 500 + 500; k++)
        acc += row[k] * ce_w1[k * 256 + t];
    part[sl][t] = acc;
    __syncthreads();
    if (tid < 256) {
        float v = part[0][tid] + part[1][tid] + part[2][tid] + part[3][tid] + ce_b1[tid];
        h1[tid] = eluf(v);
    }
    __syncthreads();
    if (tid < 256) {
        int s2 = tid >> 6, e = tid & 63;
        float a2 = 0.f;
        for (int h = s2 * 64; h < s2 * 64 + 64; h++)
            a2 += h1[h] * ce_w2[h * 64 + e];
        part[s2][e] = a2;
    }
    __syncthreads();
    if (tid < 64)
        d_ce_g[c * 64 + tid] = part[0][tid] + part[1][tid] + part[2][tid] + part[3][tid] + ce_b2[tid];
}

// ---------------- k_A: A[c,h] = ce[c,:] . w1[1:65,h] --------------------
__global__ void k_A(const float* __restrict__ g_w1)
{
    int c = blockIdx.x, tid = threadIdx.x;
    __shared__ float ces[64];
    if (tid < 64) ces[tid] = d_ce_g[c * 64 + tid];
    __syncthreads();
    float a = 0.f;
#pragma unroll 8
    for (int e = 0; e < 64; e++)
        a += ces[e] * g_w1[(1 + e) * 256 + tid];
    d_A_g[c * 256 + tid] = a;
}

// ------ k_B: B[g,h] = ge.w1[65:129] + shift*w1[129] + 128*w1[130] + b1 --
__global__ void k_B(const int* __restrict__ gidx, const float* __restrict__ shift_vec,
                    const float* __restrict__ gene_table, const float* __restrict__ g_w1,
                    const float* __restrict__ g_b1)
{
    int g = blockIdx.x, tid = threadIdx.x;
    __shared__ float ges[64];
    __shared__ float shs;
    int gs = gidx[g];
    if (tid < 64) ges[tid] = gene_table[gs * 64 + tid];
    if (tid == 0) shs = shift_vec[gs];
    __syncthreads();
    float a = g_b1[tid] + 128.0f * g_w1[130 * 256 + tid] + shs * g_w1[129 * 256 + tid];
#pragma unroll 8
    for (int e = 0; e < 64; e++)
        a += ges[e] * g_w1[(65 + e) * 256 + tid];
    d_B_g[g * 256 + tid] = a;
}

// ======================= k3: fully fused per-gene ========================
// smem layout (floats):
#define SM_CTRL   0          // 128
#define SM_RS     128        // 256
#define SM_BS     384        // 256
#define SM_QS     640        // 256
#define SM_PSUM   896        // 256
#define SM_PPA    1152       // 512
#define SM_PPB    1664       // 512
#define SM_QPART  2176       // 512
#define SM_W3A    2688       // 256
#define SM_W3B    2944       // 256
#define SM_X3     3200       // 128
#define SM_XS0    3328       // 128*68 = 8704
#define SM_XS1    12032      // 8704
#define SM_WS0    20736      // 64*264 = 16896
#define SM_WS1    37632      // 16896
#define K3_SMEM_FLOATS 54528 // 218112 bytes
#define SM_COLRED SM_WS0            // 4*256
#define SM_ROWRED (SM_WS0 + 1024)   // 4*128
#define SM_CRED   (SM_WS0 + 1536)   // 256

__global__ __launch_bounds__(512, 1) void k3(
    const float* __restrict__ ctrl, const int* __restrict__ gidx,
    const float* __restrict__ g_w1, const float* __restrict__ g_w2,
    const float* __restrict__ g_b2, const float* __restrict__ g_w3,
    const float* __restrict__ g_b3, float* __restrict__ out)
{
    extern __shared__ float sm[];
    unsigned* usm = (unsigned*)sm;
    uint32_t sbase = smem_u32(sm);

    int g = blockIdx.x, tid = threadIdx.x;
    int lane = tid & 31, w = tid >> 5;
    int lg = lane >> 2, lt = lane & 3;
    int wr = w >> 2, wc = w & 3;
    int gs = gidx[g];

    for (int i = tid; i < 128; i += 512) sm[SM_CTRL + i] = ctrl[i * Gg + gs];
    for (int i = tid; i < 256; i += 512) {
        sm[SM_RS + i]  = g_w1[i];
        sm[SM_BS + i]  = d_B_g[g * 256 + i];
        sm[SM_W3A + i] = g_w3[i];
        sm[SM_W3B + i] = g_w3[256 + i];
    }

#define CPW(kc, wofs)                                                        \
    {                                                                        \
        const float* src_ = g_w2 + (kc) * 64 * 256;                          \
        for (int i = tid; i < 4096; i += 512) {                              \
            int r_ = i >> 6, cp_ = i & 63;                                   \
            cpasync16(sbase + ((wofs) + r_ * 264 + cp_ * 4) * 4,             \
                      src_ + r_ * 256 + cp_ * 4);                            \
        }                                                                    \
        cp_commit();                                                         \
    }

#define GENX(kc, xofs, pofs)                                                 \
    {                                                                        \
        int hl_ = tid & 63;                                                  \
        int h_ = (kc) * 64 + hl_;                                            \
        float rv_ = sm[SM_RS + h_];                                          \
        float Bv_ = sm[SM_BS + h_];                                          \
        float lps_ = 0.f;                                                    \
        _Pragma("unroll 4")                                                  \
        for (int k_ = 0; k_ < 16; k_++) {                                    \
            int c_ = (tid >> 6) + 8 * k_;                                    \
            float v_ = fast_elu(sm[SM_CTRL + c_] * rv_ + d_A_g[c_ * 256 + h_] + Bv_); \
            usm[(xofs) + c_ * 68 + hl_] = __float_as_uint(v_);               \
            lps_ += v_;                                                      \
        }                                                                    \
        sm[(pofs) + hl_ * 8 + (tid >> 6)] = lps_;                            \
    }

#define REDP(kc, pofs)                                                       \
    if (tid < 64) {                                                          \
        float s_ = 0.f;                                                      \
        _Pragma("unroll")                                                    \
        for (int j_ = 0; j_ < 8; j_++) s_ += sm[(pofs) + tid * 8 + j_];      \
        sm[SM_PSUM + (kc) * 64 + tid] = s_;                                  \
    }

    CPW(0, SM_WS0);
    CPW(1, SM_WS1);
    GENX(0, SM_XS0, SM_PPA);
    cp_wait<1>();
    __syncthreads();
    REDP(0, SM_PPA);

    float acc[2][8][4];
#pragma unroll
    for (int i = 0; i < 2; i++)
#pragma unroll
        for (int j = 0; j < 8; j++)
#pragma unroll
            for (int k = 0; k < 4; k++) acc[i][j][k] = 0.f;

#pragma unroll
    for (int it = 0; it < 4; it++) {
        int xb = (it & 1) ? SM_XS1 : SM_XS0;
        int wb = (it & 1) ? SM_WS1 : SM_WS0;
#pragma unroll
        for (int ks = 0; ks < 8; ks++) {
            int k0 = ks * 8;
            unsigned a[2][4], b[8][2];
#pragma unroll
            for (int ra = 0; ra < 2; ra++) {
                int r0 = wr * 32 + ra * 16 + lg;
                a[ra][0] = usm[xb + r0 * 68 + k0 + lt];
                a[ra][1] = usm[xb + (r0 + 8) * 68 + k0 + lt];
                a[ra][2] = usm[xb + r0 * 68 + k0 + lt + 4];
                a[ra][3] = usm[xb + (r0 + 8) * 68 + k0 + lt + 4];
            }
#pragma unroll
            for (int cb = 0; cb < 8; cb++) {
                int n = wc * 64 + cb * 8 + lg;
                b[cb][0] = usm[wb + (k0 + lt) * 264 + n];
                b[cb][1] = usm[wb + (k0 + lt + 4) * 264 + n];
            }
#pragma unroll
            for (int ra = 0; ra < 2; ra++)
#pragma unroll
                for (int cb = 0; cb < 8; cb++)
                    mma_tf32(acc[ra][cb], a[ra], b[cb]);
        }
        if (it == 0) GENX(1, SM_XS1, SM_PPB);
        if (it == 1) GENX(2, SM_XS0, SM_PPA);
        if (it == 2) GENX(3, SM_XS1, SM_PPB);
        __syncthreads();
        if (it == 0) REDP(1, SM_PPB);
        if (it == 1) REDP(2, SM_PPA);
        if (it == 2) REDP(3, SM_PPB);
        if (it == 0) { CPW(2, SM_WS0); cp_wait<1>(); }
        if (it == 1) { CPW(3, SM_WS1); cp_wait<1>(); }
        if (it == 2) { cp_wait<0>(); }
        if (it < 3) __syncthreads();
    }
    __syncthreads();

    // -------- q = p @ W2b + b2 --------
    {
        int n = tid & 255, half = tid >> 8;
        float qp = 0.f;
#pragma unroll 4
        for (int h = 0; h < 128; h++) {
            int hh = half * 128 + h;
            qp += (sm[SM_PSUM + hh] * (1.f / 128.f)) * g_w2[(256 + hh) * 256 + n];
        }
        sm[SM_QPART + tid] = qp;
    }
    __syncthreads();
    if (tid < 256)
        sm[SM_QS + tid] = sm[SM_QPART + tid] + sm[SM_QPART + 256 + tid] + g_b2[tid];
    __syncthreads();

    // -------- epilogue --------
    float rsum[4] = {0.f, 0.f, 0.f, 0.f};
    float csum[16];
#pragma unroll
    for (int i = 0; i < 16; i++) csum[i] = 0.f;
#pragma unroll
    for (int cb = 0; cb < 8; cb++) {
#pragma unroll
        for (int ra = 0; ra < 2; ra++) {
#pragma unroll
            for (int jj = 0; jj < 4; jj++) {
                int col = wc * 64 + cb * 8 + 2 * lt + (jj & 1);
                float v = acc[ra][cb][jj] + sm[SM_QS + col];
                csum[cb * 2 + (jj & 1)] += v;
                rsum[ra * 2 + (jj >> 1)] += sm[SM_W3A + col] * fast_elu(v);
            }
        }
    }
#pragma unroll
    for (int m = 4; m <= 16; m <<= 1)
#pragma unroll
        for (int i = 0; i < 16; i++) csum[i] += __shfl_xor_sync(0xffffffffu, csum[i], m);
#pragma unroll
    for (int m = 1; m <= 2; m <<= 1)
#pragma unroll
        for (int i = 0; i < 4; i++) rsum[i] += __shfl_xor_sync(0xffffffffu, rsum[i], m);
    if (lg == 0) {
#pragma unroll
        for (int cb = 0; cb < 8; cb++)
#pragma unroll
            for (int j = 0; j < 2; j++)
                sm[SM_COLRED + wr * 256 + wc * 64 + cb * 8 + 2 * lt + j] = csum[cb * 2 + j];
    }
    if (lt == 0) {
#pragma unroll
        for (int ri = 0; ri < 4; ri++)
            sm[SM_ROWRED + wc * 128 + wr * 32 + (ri >> 1) * 16 + (ri & 1) * 8 + lg] = rsum[ri];
    }
    __syncthreads();

    if (tid < 256) {
        float s = sm[SM_COLRED + tid] + sm[SM_COLRED + 256 + tid] +
                  sm[SM_COLRED + 512 + tid] + sm[SM_COLRED + 768 + tid];
        float p2 = s * (1.f / 128.f);
        sm[SM_CRED + tid] = sm[SM_W3B + tid] * fast_elu(p2);
    }
    __syncthreads();
    for (int off = 128; off > 0; off >>= 1) {
        if (tid < off) sm[SM_CRED + tid] += sm[SM_CRED + tid + off];
        __syncthreads();
    }
    float cgene = sm[SM_CRED] + g_b3[0];

    if (tid < 128)
        sm[SM_X3 + tid] = sm[SM_ROWRED + tid] + sm[SM_ROWRED + 128 + tid] +
                          sm[SM_ROWRED + 256 + tid] + sm[SM_ROWRED + 384 + tid] + cgene;
    __syncthreads();
    if (tid < 128) sm[SM_PPA + tid] = sm[SM_X3 + tid];
    __syncthreads();
    for (int off = 64; off > 0; off >>= 1) {
        if (tid < off) sm[SM_PPA + tid] = fmaxf(sm[SM_PPA + tid], sm[SM_PPA + tid + off]);
        __syncthreads();
    }
    float mx = sm[SM_PPA];
    __syncthreads();
    float ev = 0.f;
    if (tid < 128) {
        ev = __expf(sm[SM_X3 + tid] - mx);
        sm[SM_PPA + tid] = ev;
    }
    __syncthreads();
    for (int off = 64; off > 0; off >>= 1) {
        if (tid < off) sm[SM_PPA + tid] += sm[SM_PPA + tid + off];
        __syncthreads();
    }
    if (tid < 128) out[tid * Gg + g] = ev / sm[SM_PPA];
}

// -------------------------------------------------------------------------
extern "C" void kernel_launch(void* const* d_in, const int* in_sizes, int n_in,
                              void* d_out, int out_size)
{
    const float* ctrl       = (const float*)d_in[0];
    const float* shift_vec  = (const float*)d_in[1];
    const int*   gidx       = (const int*)d_in[2];
    const float* ce_w1      = (const float*)d_in[3];
    const float* ce_b1      = (const float*)d_in[4];
    const float* ce_w2      = (const float*)d_in[5];
    const float* ce_b2      = (const float*)d_in[6];
    const float* gene_table = (const float*)d_in[7];
    const float* g_w1       = (const float*)d_in[8];
    const float* g_b1       = (const float*)d_in[9];
    const float* g_w2       = (const float*)d_in[10];
    const float* g_b2       = (const float*)d_in[11];
    const float* g_w3       = (const float*)d_in[12];
    const float* g_b3       = (const float*)d_in[13];
    float* out = (float*)d_out;

    cudaFuncSetAttribute(k3, cudaFuncAttributeMaxDynamicSharedMemorySize,
                         K3_SMEM_FLOATS * (int)sizeof(float));

    k_ce<<<Cc, 1024>>>(ctrl, ce_w1, ce_b1, ce_w2, ce_b2);
    k_A<<<Cc, 256>>>(g_w1);
    k_B<<<Gg, 256>>>(gidx, shift_vec, gene_table, g_w1, g_b1);
    k3<<<Gg, 512, K3_SMEM_FLOATS * sizeof(float)>>>(ctrl, gidx, g_w1, g_w2,
                                                    g_b2, g_w3, g_b3, out);
}

// round 9
// speedup vs baseline: 1.0590x; 1.0590x over previous
#include <cuda_runtime.h>
#include <cstdint>

#define Cc 128
#define Gg 2000

// ---------------- scratch (device globals; no allocation) ----------------
__device__ float d_ce_g[Cc * 64];
__device__ float d_A_g[Cc * 256];
__device__ float d_B_g[Gg * 256];
__device__ float d_p_g[Gg * 256];
__device__ float d_q_g[Gg * 256];
__device__ float d_cg_g[Gg];
__device__ float d_rr_g[2 * Gg * Cc];   // per (gene, nhalf) row-sums

__device__ __forceinline__ float eluf(float x) {
    return x > 0.f ? x : (__expf(x) - 1.f);
}
// FMA-only elu (expm1 via magic-number range reduction + poly)
__device__ __forceinline__ float fast_elu(float x) {
    float t = fmaxf(x, -17.0f);
    float nf = fmaf(t, 1.4426950408889634f, 12582912.0f);
    int   ni = __float_as_int(nf) - 0x4B400000;
    float n  = nf - 12582912.0f;
    float f = fmaf(n, -0.6931471824645996f, t);
    f = fmaf(n, 1.904654323148236e-09f, f);
    float p = 1.3981999507e-3f;
    p = fmaf(p, f, 8.3334519073e-3f);
    p = fmaf(p, f, 4.1665795894e-2f);
    p = fmaf(p, f, 1.6666665459e-1f);
    p = fmaf(p, f, 5.0000001201e-1f);
    p = fmaf(p, f, 1.0f);
    p = fmaf(p, f, 1.0f);
    float s = __int_as_float((ni + 127) << 23);
    float r = fmaf(p, s, -1.0f);
    return x > 0.f ? x : r;
}

__device__ __forceinline__ void mma_tf32(float* acc, const unsigned* a, const unsigned* b) {
    asm volatile(
        "mma.sync.aligned.m16n8k8.row.col.f32.tf32.tf32.f32 "
        "{%0,%1,%2,%3}, {%4,%5,%6,%7}, {%8,%9}, {%0,%1,%2,%3};"
        : "+f"(acc[0]), "+f"(acc[1]), "+f"(acc[2]), "+f"(acc[3])
        : "r"(a[0]), "r"(a[1]), "r"(a[2]), "r"(a[3]), "r"(b[0]), "r"(b[1]));
}
__device__ __forceinline__ uint32_t smem_u32(const void* p) {
    uint32_t a;
    asm("{ .reg .u64 t; cvta.to.shared.u64 t, %1; cvt.u32.u64 %0, t; }" : "=r"(a) : "l"(p));
    return a;
}
__device__ __forceinline__ void cpasync16(uint32_t dst, const void* src) {
    asm volatile("cp.async.ca.shared.global [%0], [%1], 16;" :: "r"(dst), "l"(src));
}
__device__ __forceinline__ void cp_commit() { asm volatile("cp.async.commit_group;"); }
template <int N> __device__ __forceinline__ void cp_wait() {
    asm volatile("cp.async.wait_group %0;" :: "n"(N));
}

// ---------------- k_ce ----------------
__global__ __launch_bounds__(1024) void k_ce(
    const float* __restrict__ ctrl, const float* __restrict__ ce_w1,
    const float* __restrict__ ce_b1, const float* __restrict__ ce_w2,
    const float* __restrict__ ce_b2)
{
    int c = blockIdx.x, tid = threadIdx.x;
    __shared__ float row[Gg];
    __shared__ float part[4][256];
    __shared__ float h1[256];
    for (int i = tid; i < Gg; i += 1024) row[i] = ctrl[c * Gg + i];
    __syncthreads();
    int sl = tid >> 8, t = tid & 255;
    float acc = 0.f;
    for (int k = sl * 500; k < sl * 500 + 500; k++)
        acc += row[k] * ce_w1[k * 256 + t];
    part[sl][t] = acc;
    __syncthreads();
    if (tid < 256) {
        float v = part[0][tid] + part[1][tid] + part[2][tid] + part[3][tid] + ce_b1[tid];
        h1[tid] = eluf(v);
    }
    __syncthreads();
    if (tid < 256) {
        int s2 = tid >> 6, e = tid & 63;
        float a2 = 0.f;
        for (int h = s2 * 64; h < s2 * 64 + 64; h++)
            a2 += h1[h] * ce_w2[h * 64 + e];
        part[s2][e] = a2;
    }
    __syncthreads();
    if (tid < 64)
        d_ce_g[c * 64 + tid] = part[0][tid] + part[1][tid] + part[2][tid] + part[3][tid] + ce_b2[tid];
}

// ---------------- k_A ----------------
__global__ void k_A(const float* __restrict__ g_w1)
{
    int c = blockIdx.x, tid = threadIdx.x;
    __shared__ float ces[64];
    if (tid < 64) ces[tid] = d_ce_g[c * 64 + tid];
    __syncthreads();
    float a = 0.f;
#pragma unroll 8
    for (int e = 0; e < 64; e++)
        a += ces[e] * g_w1[(1 + e) * 256 + tid];
    d_A_g[c * 256 + tid] = a;
}

// ---------------- k_B ----------------
__global__ void k_B(const int* __restrict__ gidx, const float* __restrict__ shift_vec,
                    const float* __restrict__ gene_table, const float* __restrict__ g_w1,
                    const float* __restrict__ g_b1)
{
    int g = blockIdx.x, tid = threadIdx.x;
    __shared__ float ges[64];
    __shared__ float shs;
    int gs = gidx[g];
    if (tid < 64) ges[tid] = gene_table[gs * 64 + tid];
    if (tid == 0) shs = shift_vec[gs];
    __syncthreads();
    float a = g_b1[tid] + 128.0f * g_w1[130 * 256 + tid] + shs * g_w1[129 * 256 + tid];
#pragma unroll 8
    for (int e = 0; e < 64; e++)
        a += ges[e] * g_w1[(65 + e) * 256 + tid];
    d_B_g[g * 256 + tid] = a;
}

// ---- k_p: p[g,h] = mean_c elu(ctrl*r + A + B) ----
__global__ __launch_bounds__(256) void k_p(
    const float* __restrict__ ctrl, const int* __restrict__ gidx,
    const float* __restrict__ g_w1)
{
    int g = blockIdx.x, tid = threadIdx.x;
    __shared__ float cs[128];
    int gs = gidx[g];
    if (tid < 128) cs[tid] = ctrl[tid * Gg + gs];
    __syncthreads();
    float rv = g_w1[tid];
    float Bv = d_B_g[g * 256 + tid];
    float s = 0.f;
#pragma unroll 4
    for (int c = 0; c < 128; c++)
        s += eluf(cs[c] * rv + d_A_g[c * 256 + tid] + Bv);
    d_p_g[g * 256 + tid] = s * (1.f / 128.f);
}

// ---- k_q: q = p@W2b + b2 ; p2 = p@W2a + q ; cg = sum w3b*elu(p2) + b3 ----
__global__ __launch_bounds__(256) void k_q(
    const float* __restrict__ g_w2, const float* __restrict__ g_b2,
    const float* __restrict__ g_w3, const float* __restrict__ g_b3)
{
    __shared__ float ps[8][256];
    __shared__ float red[8][256];
    int g0 = blockIdx.x * 8, tid = threadIdx.x;
    for (int i = 0; i < 8; i++) ps[i][tid] = d_p_g[(g0 + i) * 256 + tid];
    __syncthreads();
    float qa[8], pa[8];
#pragma unroll
    for (int i = 0; i < 8; i++) { qa[i] = 0.f; pa[i] = 0.f; }
    for (int k = 0; k < 256; k++) {
        float wa = g_w2[k * 256 + tid];
        float wb = g_w2[(256 + k) * 256 + tid];
#pragma unroll
        for (int i = 0; i < 8; i++) {
            float pv = ps[i][k];
            qa[i] = fmaf(pv, wb, qa[i]);
            pa[i] = fmaf(pv, wa, pa[i]);
        }
    }
    float b2v = g_b2[tid];
    float w3bv = g_w3[256 + tid];
#pragma unroll
    for (int i = 0; i < 8; i++) {
        float q = qa[i] + b2v;
        d_q_g[(g0 + i) * 256 + tid] = q;
        float p2 = pa[i] + q;
        red[i][tid] = w3bv * eluf(p2);
    }
    __syncthreads();
    for (int off = 128; off > 0; off >>= 1) {
        if (tid < off)
#pragma unroll
            for (int i = 0; i < 8; i++) red[i][tid] += red[i][tid + off];
        __syncthreads();
    }
    if (tid < 8) d_cg_g[g0 + tid] = red[tid][0] + g_b3[0];
}

// ============ k3: per-(gene, N-half) GEMM, 256 thr, 2 blocks/SM ==========
// K chunks of 32 (8 chunks). W ring: 3 bufs [32 x 132]; X: 2 bufs [128 x 36].
#define WBUF(i)  ((i) * 4224)            // 3 x 4224
#define XBUF(i)  (12672 + (i) * 4608)    // 2 x 4608
#define SM_CTRL  21888                   // 128
#define SM_RS    22016                   // 256
#define SM_BS    22272                   // 256
#define SM_QS    22528                   // 128
#define SM_W3A   22656                   // 128
#define SM_RR    22784                   // 512
#define K3_WORDS 23296                   // 93184 bytes

__global__ __launch_bounds__(256, 2) void k3(
    const float* __restrict__ ctrl, const int* __restrict__ gidx,
    const float* __restrict__ g_w1, const float* __restrict__ g_w2,
    const float* __restrict__ g_w3)
{
    extern __shared__ float sm[];
    unsigned* usm = (unsigned*)sm;
    uint32_t sbase = smem_u32(sm);

    int bi = blockIdx.x;
    int g = bi >> 1, nh = bi & 1;
    int tid = threadIdx.x;
    int lane = tid & 31, w = tid >> 5;
    int lg = lane >> 2, lt = lane & 3;
    int wr = w >> 2, wc = w & 3;          // 2 x 4 warp grid; tile 64r x 32c
    int gs = gidx[g];

    // prologue
    if (tid < 128) sm[SM_CTRL + tid] = ctrl[tid * Gg + gs];
    sm[SM_RS + tid] = g_w1[tid];
    sm[SM_BS + tid] = d_B_g[g * 256 + tid];
    if (tid < 128) {
        sm[SM_QS + tid]  = d_q_g[g * 256 + nh * 128 + tid];
        sm[SM_W3A + tid] = g_w3[nh * 128 + tid];
    }
    // RACE FIX: GENX(0) below reads SM_CTRL/SM_RS/SM_BS slots written by
    // OTHER threads; must be visible before any read.
    __syncthreads();

    auto CPW = [&](int kc, int buf) {
        for (int i = tid; i < 1024; i += 256) {
            int row = i >> 5, seg = i & 31;
            cpasync16(sbase + (WBUF(buf) + row * 132 + seg * 4) * 4,
                      g_w2 + (kc * 32 + row) * 256 + nh * 128 + seg * 4);
        }
        cp_commit();
    };
    auto GENX = [&](int kc, int xofs) {
        int kl = tid & 31, c0 = tid >> 5;
        int h = kc * 32 + kl;
        float rv = sm[SM_RS + h], Bv = sm[SM_BS + h];
#pragma unroll
        for (int j = 0; j < 16; j++) {
            int c = c0 + 8 * j;
            float v = fast_elu(sm[SM_CTRL + c] * rv + d_A_g[c * 256 + h] + Bv);
            usm[xofs + c * 36 + kl] = __float_as_uint(v);
        }
    };

    CPW(0, 0);
    CPW(1, 1);
    GENX(0, XBUF(0));
    cp_wait<1>();
    __syncthreads();

    float acc[4][4][4];
#pragma unroll
    for (int i = 0; i < 4; i++)
#pragma unroll
        for (int j = 0; j < 4; j++)
#pragma unroll
            for (int k = 0; k < 4; k++) acc[i][j][k] = 0.f;

#pragma unroll
    for (int kc = 0; kc < 8; kc++) {
        const int xb = XBUF(kc & 1);
        const int wb = WBUF(kc % 3);
        // MMA on chunk kc (reads X[kc&1], W[kc%3])
#pragma unroll
        for (int ks = 0; ks < 4; ks++) {
            int k0 = ks * 8;
            unsigned a[4][4], b[4][2];
#pragma unroll
            for (int ra = 0; ra < 4; ra++) {
                int r0 = wr * 64 + ra * 16 + lg;
                a[ra][0] = usm[xb + r0 * 36 + k0 + lt];
                a[ra][1] = usm[xb + (r0 + 8) * 36 + k0 + lt];
                a[ra][2] = usm[xb + r0 * 36 + k0 + lt + 4];
                a[ra][3] = usm[xb + (r0 + 8) * 36 + k0 + lt + 4];
            }
#pragma unroll
            for (int cb = 0; cb < 4; cb++) {
                int n = wc * 32 + cb * 8 + lg;
                b[cb][0] = usm[wb + (k0 + lt) * 132 + n];
                b[cb][1] = usm[wb + (k0 + lt + 4) * 132 + n];
            }
#pragma unroll
            for (int ra = 0; ra < 4; ra++)
#pragma unroll
                for (int cb = 0; cb < 4; cb++)
                    mma_tf32(acc[ra][cb], a[ra], b[cb]);
        }
        // overlap: write disjoint buffers while MMA(kc) proceeds in other warps
        if (kc < 7) GENX(kc + 1, XBUF((kc + 1) & 1));
        if (kc < 6) CPW(kc + 2, (kc + 2) % 3);
        if (kc < 6) { cp_wait<1>(); }
        else if (kc == 6) { cp_wait<0>(); }
        __syncthreads();
    }

    // -------- epilogue: row sums of elu(x2 + q) * w3a --------
    float rsum[4][2];
#pragma unroll
    for (int i = 0; i < 4; i++) { rsum[i][0] = 0.f; rsum[i][1] = 0.f; }
#pragma unroll
    for (int cb = 0; cb < 4; cb++) {
#pragma unroll
        for (int ra = 0; ra < 4; ra++) {
#pragma unroll
            for (int jj = 0; jj < 4; jj++) {
                int col = wc * 32 + cb * 8 + 2 * lt + (jj & 1);
                float v = acc[ra][cb][jj] + sm[SM_QS + col];
                rsum[ra][jj >> 1] += sm[SM_W3A + col] * fast_elu(v);
            }
        }
    }
#pragma unroll
    for (int m = 1; m <= 2; m <<= 1)
#pragma unroll
        for (int ra = 0; ra < 4; ra++) {
            rsum[ra][0] += __shfl_xor_sync(0xffffffffu, rsum[ra][0], m);
            rsum[ra][1] += __shfl_xor_sync(0xffffffffu, rsum[ra][1], m);
        }
    if (lt == 0) {
#pragma unroll
        for (int ra = 0; ra < 4; ra++) {
            sm[SM_RR + wc * 128 + wr * 64 + ra * 16 + lg]     = rsum[ra][0];
            sm[SM_RR + wc * 128 + wr * 64 + ra * 16 + 8 + lg] = rsum[ra][1];
        }
    }
    __syncthreads();
    if (tid < 128)
        d_rr_g[bi * 128 + tid] = sm[SM_RR + tid] + sm[SM_RR + 128 + tid] +
                                 sm[SM_RR + 256 + tid] + sm[SM_RR + 384 + tid];
}

// ---- k4: combine halves, + cgene, softmax over cells ----
__global__ __launch_bounds__(128) void k4(float* __restrict__ out)
{
    int g = blockIdx.x, tid = threadIdx.x;
    __shared__ float buf[128];
    float v = d_rr_g[(2 * g) * 128 + tid] + d_rr_g[(2 * g + 1) * 128 + tid] + d_cg_g[g];
    buf[tid] = v;
    __syncthreads();
    for (int off = 64; off > 0; off >>= 1) {
        if (tid < off) buf[tid] = fmaxf(buf[tid], buf[tid + off]);
        __syncthreads();
    }
    float m = buf[0];
    __syncthreads();
    float e = __expf(v - m);
    buf[tid] = e;
    __syncthreads();
    for (int off = 64; off > 0; off >>= 1) {
        if (tid < off) buf[tid] += buf[tid + off];
        __syncthreads();
    }
    out[tid * Gg + g] = e / buf[0];
}

// -------------------------------------------------------------------------
extern "C" void kernel_launch(void* const* d_in, const int* in_sizes, int n_in,
                              void* d_out, int out_size)
{
    const float* ctrl       = (const float*)d_in[0];
    const float* shift_vec  = (const float*)d_in[1];
    const int*   gidx       = (const int*)d_in[2];
    const float* ce_w1      = (const float*)d_in[3];
    const float* ce_b1      = (const float*)d_in[4];
    const float* ce_w2      = (const float*)d_in[5];
    const float* ce_b2      = (const float*)d_in[6];
    const float* gene_table = (const float*)d_in[7];
    const float* g_w1       = (const float*)d_in[8];
    const float* g_b1       = (const float*)d_in[9];
    const float* g_w2       = (const float*)d_in[10];
    const float* g_b2       = (const float*)d_in[11];
    const float* g_w3       = (const float*)d_in[12];
    const float* g_b3       = (const float*)d_in[13];
    float* out = (float*)d_out;

    cudaFuncSetAttribute(k3, cudaFuncAttributeMaxDynamicSharedMemorySize,
                         K3_WORDS * (int)sizeof(float));

    k_ce<<<Cc, 1024>>>(ctrl, ce_w1, ce_b1, ce_w2, ce_b2);
    k_A<<<Cc, 256>>>(g_w1);
    k_B<<<Gg, 256>>>(gidx, shift_vec, gene_table, g_w1, g_b1);
    k_p<<<Gg, 256>>>(ctrl, gidx, g_w1);
    k_q<<<Gg / 8, 256>>>(g_w2, g_b2, g_w3, g_b3);
    k3<<<2 * Gg, 256, K3_WORDS * sizeof(float)>>>(ctrl, gidx, g_w1, g_w2, g_w3);
    k4<<<Gg, 128>>>(out);
}

// round 10
// speedup vs baseline: 1.6018x; 1.5125x over previous
#include <cuda_runtime.h>
#include <cuda_bf16.h>
#include <cstdint>

#define Cc 128
#define Gg 2000

// ---------------- scratch (device globals; no allocation) ----------------
__device__ float d_ce_g[Cc * 64];
__device__ float d_A_g[Cc * 256];
__device__ float d_B_g[Gg * 256];
__device__ float d_p_g[Gg * 256];
__device__ float d_q_g[Gg * 256];
__device__ float d_cg_g[Gg];
__device__ float d_x3_g[Gg * Cc];
__device__ __nv_bfloat16 d_Wt16[256 * 256];   // W2a^T as bf16, [n][k]

__device__ __forceinline__ float eluf(float x) {
    return x > 0.f ? x : (__expf(x) - 1.f);
}
// branchless elu: max(x,0) + e^{min(x,0)} - 1  (exact on both branches)
__device__ __forceinline__ float melu(float x) {
    return fmaxf(x, 0.f) + __expf(fminf(x, 0.f)) - 1.f;
}

__device__ __forceinline__ void mma_bf16(float* acc, const unsigned* a, const unsigned* b) {
    asm volatile(
        "mma.sync.aligned.m16n8k16.row.col.f32.bf16.bf16.f32 "
        "{%0,%1,%2,%3}, {%4,%5,%6,%7}, {%8,%9}, {%0,%1,%2,%3};"
        : "+f"(acc[0]), "+f"(acc[1]), "+f"(acc[2]), "+f"(acc[3])
        : "r"(a[0]), "r"(a[1]), "r"(a[2]), "r"(a[3]), "r"(b[0]), "r"(b[1]));
}
__device__ __forceinline__ void ldsm4(unsigned& r0, unsigned& r1, unsigned& r2, unsigned& r3,
                                      uint32_t addr) {
    asm volatile("ldmatrix.sync.aligned.m8n8.x4.shared.b16 {%0,%1,%2,%3}, [%4];"
                 : "=r"(r0), "=r"(r1), "=r"(r2), "=r"(r3) : "r"(addr));
}
__device__ __forceinline__ uint32_t smem_u32(const void* p) {
    uint32_t a;
    asm("{ .reg .u64 t; cvta.to.shared.u64 t, %1; cvt.u32.u64 %0, t; }" : "=r"(a) : "l"(p));
    return a;
}
__device__ __forceinline__ void cpasync16(uint32_t dst, const void* src) {
    asm volatile("cp.async.ca.shared.global [%0], [%1], 16;" :: "r"(dst), "l"(src));
}
__device__ __forceinline__ void cp_commit() { asm volatile("cp.async.commit_group;"); }
template <int N> __device__ __forceinline__ void cp_wait() {
    asm volatile("cp.async.wait_group %0;" :: "n"(N));
}

// ---------------- k_ce ----------------
__global__ __launch_bounds__(1024) void k_ce(
    const float* __restrict__ ctrl, const float* __restrict__ ce_w1,
    const float* __restrict__ ce_b1, const float* __restrict__ ce_w2,
    const float* __restrict__ ce_b2)
{
    int c = blockIdx.x, tid = threadIdx.x;
    __shared__ float row[Gg];
    __shared__ float part[4][256];
    __shared__ float h1[256];
    for (int i = tid; i < Gg; i += 1024) row[i] = ctrl[c * Gg + i];
    __syncthreads();
    int sl = tid >> 8, t = tid & 255;
    float acc = 0.f;
    for (int k = sl * 500; k < sl * 500 + 500; k++)
        acc += row[k] * ce_w1[k * 256 + t];
    part[sl][t] = acc;
    __syncthreads();
    if (tid < 256) {
        float v = part[0][tid] + part[1][tid] + part[2][tid] + part[3][tid] + ce_b1[tid];
        h1[tid] = eluf(v);
    }
    __syncthreads();
    if (tid < 256) {
        int s2 = tid >> 6, e = tid & 63;
        float a2 = 0.f;
        for (int h = s2 * 64; h < s2 * 64 + 64; h++)
            a2 += h1[h] * ce_w2[h * 64 + e];
        part[s2][e] = a2;
    }
    __syncthreads();
    if (tid < 64)
        d_ce_g[c * 64 + tid] = part[0][tid] + part[1][tid] + part[2][tid] + part[3][tid] + ce_b2[tid];
}

// ---------------- k_A ----------------
__global__ void k_A(const float* __restrict__ g_w1)
{
    int c = blockIdx.x, tid = threadIdx.x;
    __shared__ float ces[64];
    if (tid < 64) ces[tid] = d_ce_g[c * 64 + tid];
    __syncthreads();
    float a = 0.f;
#pragma unroll 8
    for (int e = 0; e < 64; e++)
        a += ces[e] * g_w1[(1 + e) * 256 + tid];
    d_A_g[c * 256 + tid] = a;
}

// ---------------- k_B ----------------
__global__ void k_B(const int* __restrict__ gidx, const float* __restrict__ shift_vec,
                    const float* __restrict__ gene_table, const float* __restrict__ g_w1,
                    const float* __restrict__ g_b1)
{
    int g = blockIdx.x, tid = threadIdx.x;
    __shared__ float ges[64];
    __shared__ float shs;
    int gs = gidx[g];
    if (tid < 64) ges[tid] = gene_table[gs * 64 + tid];
    if (tid == 0) shs = shift_vec[gs];
    __syncthreads();
    float a = g_b1[tid] + 128.0f * g_w1[130 * 256 + tid] + shs * g_w1[129 * 256 + tid];
#pragma unroll 8
    for (int e = 0; e < 64; e++)
        a += ges[e] * g_w1[(65 + e) * 256 + tid];
    d_B_g[g * 256 + tid] = a;
}

// ---- k_T: tiled transpose+convert W2a -> d_Wt16 bf16 [n][k] ----
__global__ __launch_bounds__(256) void k_T(const float* __restrict__ g_w2)
{
    __shared__ float tile[32][33];
    int bx = blockIdx.x & 7, by = blockIdx.x >> 3;
    int tx = threadIdx.x & 31, ty = threadIdx.x >> 5;
    int k0 = bx * 32, n0 = by * 32;
#pragma unroll
    for (int p = 0; p < 4; p++)
        tile[ty + 8 * p][tx] = g_w2[(k0 + ty + 8 * p) * 256 + n0 + tx];
    __syncthreads();
#pragma unroll
    for (int p = 0; p < 4; p++)
        d_Wt16[(n0 + ty + 8 * p) * 256 + k0 + tx] = __float2bfloat16(tile[tx][ty + 8 * p]);
}

// ---- k_p: p[g,h] = mean_c elu(ctrl*r + A + B) ----
__global__ __launch_bounds__(256) void k_p(
    const float* __restrict__ ctrl, const int* __restrict__ gidx,
    const float* __restrict__ g_w1)
{
    int g = blockIdx.x, tid = threadIdx.x;
    __shared__ float cs[128];
    int gs = gidx[g];
    if (tid < 128) cs[tid] = ctrl[tid * Gg + gs];
    __syncthreads();
    float rv = g_w1[tid];
    float Bv = d_B_g[g * 256 + tid];
    float s = 0.f;
#pragma unroll 8
    for (int c = 0; c < 128; c++)
        s += melu(cs[c] * rv + d_A_g[c * 256 + tid] + Bv);
    d_p_g[g * 256 + tid] = s * (1.f / 128.f);
}

// ---- k_q: q = p@W2b + b2 ; p2 = p@W2a + q ; cg = sum w3b*elu(p2) + b3 ----
__global__ __launch_bounds__(256) void k_q(
    const float* __restrict__ g_w2, const float* __restrict__ g_b2,
    const float* __restrict__ g_w3, const float* __restrict__ g_b3)
{
    __shared__ float ps[8][256];
    __shared__ float red[8][256];
    int g0 = blockIdx.x * 8, tid = threadIdx.x;
    for (int i = 0; i < 8; i++) ps[i][tid] = d_p_g[(g0 + i) * 256 + tid];
    __syncthreads();
    float qa[8], pa[8];
#pragma unroll
    for (int i = 0; i < 8; i++) { qa[i] = 0.f; pa[i] = 0.f; }
    for (int k = 0; k < 256; k++) {
        float wa = g_w2[k * 256 + tid];
        float wb = g_w2[(256 + k) * 256 + tid];
#pragma unroll
        for (int i = 0; i < 8; i++) {
            float pv = ps[i][k];
            qa[i] = fmaf(pv, wb, qa[i]);
            pa[i] = fmaf(pv, wa, pa[i]);
        }
    }
    float b2v = g_b2[tid];
    float w3bv = g_w3[256 + tid];
#pragma unroll
    for (int i = 0; i < 8; i++) {
        float q = qa[i] + b2v;
        d_q_g[(g0 + i) * 256 + tid] = q;
        float p2 = pa[i] + q;
        red[i][tid] = w3bv * eluf(p2);
    }
    __syncthreads();
    for (int off = 128; off > 0; off >>= 1) {
        if (tid < off)
#pragma unroll
            for (int i = 0; i < 8; i++) red[i][tid] += red[i][tid + off];
        __syncthreads();
    }
    if (tid < 8) d_cg_g[g0 + tid] = red[tid][0] + g_b3[0];
}

// ======= k3: per-(gene, M-half) bf16 GEMM via ldmatrix + mma.m16n8k16 =====
// Block: 64 cells x 256 cols. W ring 3 x [256 n][20w]; X 2 x [64 c][20w] bf16;
// A-chunk ring 2 x [64 c][36w] f32.
#define WBASE   0
#define WBUFW   5120
#define XBASE   15360
#define XBUFW   1280
#define ABASE   17920
#define ABUFW   2304
#define SM_CTRL 22528
#define SM_RS   22592
#define SM_BS   22848
#define SM_QS   23104
#define SM_W3A  23360
#define SM_RR   23616
#define K3_WORDS 23872   // 95488 bytes

__global__ __launch_bounds__(256, 2) void k3(
    const float* __restrict__ ctrl, const int* __restrict__ gidx,
    const float* __restrict__ g_w1, const float* __restrict__ g_w3)
{
    extern __shared__ float sm[];
    unsigned* usm = (unsigned*)sm;
    uint32_t sbase = smem_u32(sm);

    int bi = blockIdx.x;
    int g = bi >> 1, mh = bi & 1;
    int tid = threadIdx.x;
    int lane = tid & 31, w = tid >> 5;
    int lg = lane >> 2, lt = lane & 3;
    int wr = w >> 2, wc = w & 3;          // 2 x 4 warps; warp tile 32 rows x 64 cols
    int m8 = lane >> 3, r8 = lane & 7;    // ldmatrix sub-matrix / row
    int gs = gidx[g];

    // prologue scalars
    if (tid < 64) sm[SM_CTRL + tid] = ctrl[(mh * 64 + tid) * Gg + gs];
    sm[SM_RS + tid]  = g_w1[tid];
    sm[SM_BS + tid]  = d_B_g[g * 256 + tid];
    sm[SM_QS + tid]  = d_q_g[g * 256 + tid];
    sm[SM_W3A + tid] = g_w3[tid];

    auto CPW = [&](int kc, int buf) {
        for (int i = tid; i < 1024; i += 256) {
            int row = i >> 2, seg = i & 3;
            cpasync16(sbase + (WBASE + buf * WBUFW + row * 20 + seg * 4) * 4,
                      d_Wt16 + row * 256 + kc * 32 + seg * 8);
        }
    };
    auto CPA = [&](int kc, int buf) {
        for (int i = tid; i < 512; i += 256) {
            int row = i >> 3, seg = i & 7;
            cpasync16(sbase + (ABASE + buf * ABUFW + row * 36 + seg * 4) * 4,
                      d_A_g + (mh * 64 + row) * 256 + kc * 32 + seg * 4);
        }
    };
    auto GENX = [&](int kc, int xbuf) {
        int xw = XBASE + xbuf * XBUFW;
        int ab = ABASE + (kc & 1) * ABUFW;
        int kp = tid & 15, cb0 = tid >> 4;
        int h0 = kc * 32 + 2 * kp;
        float2 rsv = *(float2*)(sm + SM_RS + h0);
        float2 bsv = *(float2*)(sm + SM_BS + h0);
#pragma unroll
        for (int j = 0; j < 4; j++) {
            int c = cb0 + 16 * j;
            float cv = sm[SM_CTRL + c];
            float2 av = *(float2*)(sm + ab + c * 36 + 2 * kp);
            float v0 = melu(fmaf(cv, rsv.x, av.x + bsv.x));
            float v1 = melu(fmaf(cv, rsv.y, av.y + bsv.y));
            unsigned pr;
            asm("cvt.rn.bf16x2.f32 %0, %1, %2;" : "=r"(pr) : "f"(v1), "f"(v0));
            usm[xw + c * 20 + kp] = pr;
        }
    };

    CPW(0, 0); CPA(0, 0); cp_commit();
    CPW(1, 1); CPA(1, 1); cp_commit();
    cp_wait<1>();
    __syncthreads();     // scalars + chunk-0 copies visible
    GENX(0, 0);
    __syncthreads();

    float acc[2][8][4];
#pragma unroll
    for (int i = 0; i < 2; i++)
#pragma unroll
        for (int j = 0; j < 8; j++)
#pragma unroll
            for (int k = 0; k < 4; k++) acc[i][j][k] = 0.f;

#pragma unroll
    for (int kc = 0; kc < 8; kc++) {
        uint32_t xbb = sbase + (XBASE + (kc & 1) * XBUFW) * 4;
        uint32_t wbb = sbase + (WBASE + (kc % 3) * WBUFW) * 4;
#pragma unroll
        for (int ks = 0; ks < 2; ks++) {
            int k0b = ks * 32;  // byte offset of k0=16*ks (bf16)
            unsigned a[2][4], b[8][2];
#pragma unroll
            for (int ra = 0; ra < 2; ra++) {
                uint32_t addr = xbb + (wr * 32 + ra * 16 + (m8 & 1) * 8 + r8) * 80
                              + k0b + (m8 >> 1) * 16;
                ldsm4(a[ra][0], a[ra][1], a[ra][2], a[ra][3], addr);
            }
#pragma unroll
            for (int cbp = 0; cbp < 4; cbp++) {
                uint32_t addr = wbb + (wc * 64 + (2 * cbp + (m8 >> 1)) * 8 + r8) * 80
                              + k0b + (m8 & 1) * 16;
                ldsm4(b[2 * cbp][0], b[2 * cbp][1], b[2 * cbp + 1][0], b[2 * cbp + 1][1], addr);
            }
#pragma unroll
            for (int ra = 0; ra < 2; ra++)
#pragma unroll
                for (int cb = 0; cb < 8; cb++)
                    mma_bf16(acc[ra][cb], a[ra], b[cb]);
        }
        if (kc < 6) { CPW(kc + 2, (kc + 2) % 3); CPA(kc + 2, kc & 1); cp_commit(); }
        if (kc < 6) { cp_wait<1>(); }
        else if (kc == 6) { cp_wait<0>(); }
        if (kc < 7) GENX(kc + 1, (kc + 1) & 1);
        __syncthreads();
    }

    // -------- epilogue: full row sums of w3a * elu(x2 + q) --------
    float rsum[2][2];
    rsum[0][0] = rsum[0][1] = rsum[1][0] = rsum[1][1] = 0.f;
#pragma unroll
    for (int ra = 0; ra < 2; ra++) {
#pragma unroll
        for (int cb = 0; cb < 8; cb++) {
#pragma unroll
            for (int jj = 0; jj < 4; jj++) {
                int col = wc * 64 + cb * 8 + 2 * lt + (jj & 1);
                float v = acc[ra][cb][jj] + sm[SM_QS + col];
                rsum[ra][jj >> 1] += sm[SM_W3A + col] * melu(v);
            }
        }
    }
#pragma unroll
    for (int m = 1; m <= 2; m <<= 1)
#pragma unroll
        for (int ra = 0; ra < 2; ra++) {
            rsum[ra][0] += __shfl_xor_sync(0xffffffffu, rsum[ra][0], m);
            rsum[ra][1] += __shfl_xor_sync(0xffffffffu, rsum[ra][1], m);
        }
    if (lt == 0) {
#pragma unroll
        for (int ra = 0; ra < 2; ra++) {
            sm[SM_RR + wc * 64 + wr * 32 + ra * 16 + lg]     = rsum[ra][0];
            sm[SM_RR + wc * 64 + wr * 32 + ra * 16 + 8 + lg] = rsum[ra][1];
        }
    }
    __syncthreads();
    if (tid < 64)
        d_x3_g[g * 128 + mh * 64 + tid] =
            sm[SM_RR + tid] + sm[SM_RR + 64 + tid] +
            sm[SM_RR + 128 + tid] + sm[SM_RR + 192 + tid];
}

// ---- k4: + cgene, softmax over cells ----
__global__ __launch_bounds__(128) void k4(float* __restrict__ out)
{
    int g = blockIdx.x, tid = threadIdx.x;
    __shared__ float buf[128];
    float v = d_x3_g[g * 128 + tid] + d_cg_g[g];
    buf[tid] = v;
    __syncthreads();
    for (int off = 64; off > 0; off >>= 1) {
        if (tid < off) buf[tid] = fmaxf(buf[tid], buf[tid + off]);
        __syncthreads();
    }
    float m = buf[0];
    __syncthreads();
    float e = __expf(v - m);
    buf[tid] = e;
    __syncthreads();
    for (int off = 64; off > 0; off >>= 1) {
        if (tid < off) buf[tid] += buf[tid + off];
        __syncthreads();
    }
    out[tid * Gg + g] = e / buf[0];
}

// -------------------------------------------------------------------------
extern "C" void kernel_launch(void* const* d_in, const int* in_sizes, int n_in,
                              void* d_out, int out_size)
{
    const float* ctrl       = (const float*)d_in[0];
    const float* shift_vec  = (const float*)d_in[1];
    const int*   gidx       = (const int*)d_in[2];
    const float* ce_w1      = (const float*)d_in[3];
    const float* ce_b1      = (const float*)d_in[4];
    const float* ce_w2      = (const float*)d_in[5];
    const float* ce_b2      = (const float*)d_in[6];
    const float* gene_table = (const float*)d_in[7];
    const float* g_w1       = (const float*)d_in[8];
    const float* g_b1       = (const float*)d_in[9];
    const float* g_w2       = (const float*)d_in[10];
    const float* g_b2       = (const float*)d_in[11];
    const float* g_w3       = (const float*)d_in[12];
    const float* g_b3       = (const float*)d_in[13];
    float* out = (float*)d_out;

    cudaFuncSetAttribute(k3, cudaFuncAttributeMaxDynamicSharedMemorySize,
                         K3_WORDS * (int)sizeof(float));

    k_ce<<<Cc, 1024>>>(ctrl, ce_w1, ce_b1, ce_w2, ce_b2);
    k_A<<<Cc, 256>>>(g_w1);
    k_B<<<Gg, 256>>>(gidx, shift_vec, gene_table, g_w1, g_b1);
    k_T<<<64, 256>>>(g_w2);
    k_p<<<Gg, 256>>>(ctrl, gidx, g_w1);
    k_q<<<Gg / 8, 256>>>(g_w2, g_b2, g_w3, g_b3);
    k3<<<2 * Gg, 256, K3_WORDS * sizeof(float)>>>(ctrl, gidx, g_w1, g_w3);
    k4<<<Gg, 128>>>(out);
}